// round 16
// baseline (speedup 1.0000x reference)
#include <cuda_runtime.h>
#include <cuda_bf16.h>
#include <cstdint>

#define GAIN   1.6778523489932886f   /* 1/0.596 */
#define INV058 1.3130643285972254f   /* 1/sqrt(0.7^2+0.3^2) */
#define EPSN   1e-4f

typedef unsigned long long ull;
typedef __nv_bfloat16 bf16;

/* ---------------- static device scratch (no allocations allowed) -------- */
__device__ __align__(16) float g_wpool[15230976];
__device__ __align__(16) float g_xn[33554432];
__device__ __align__(16) float g_xs[33554432];    /* bf16 planes: hi | lo   */
__device__ __align__(16) float g_bufA[67108864];
__device__ __align__(16) float g_bufB[67108864];  /* bf16 planes            */
__device__ __align__(16) float g_h[33554432];
__device__ __align__(16) float g_pool[8388608];   /* bf16 planes            */
__device__ __align__(16) float g_x[16777216];
__device__ __align__(16) bf16 g_wbf[29360128];    /* seq weights: hi | lo   */
__device__ __align__(16) bf16 g_cwbf[1048576];    /* conv weights: hi | lo  */

#define XS_LO   33554432
#define BUFB_LO 67108864
#define POOL_LO 8388608

/* fp32 weight pool offsets (depthwise weights only) */
#define O_C0WD 8192
#define O_C1WD 59264
#define O_C2WD 259712
#define O_DW   4723840

/* bf16 conv-weight hi offsets in g_cwbf; lo at +CWLO */
#define CWLO 516096
#define CWH_C0W1 0
#define CWH_C0W2 8192
#define CWH_C0DN 16384
#define CWH_C1W1 24576
#define CWH_C1W2 57344
#define CWH_C1DN 90112
#define CWH_C2W1 122880
#define CWH_C2W2 253952
#define CWH_C2DN 385024

/* bf16 seq-weight hi offsets in g_wbf; lo at +WLO */
#define WLO 14680064
#define WH_HG(i)  ((i) * 1048576)
#define WH_GRU(i) (4194304 + (i) * 2097152)
#define WH_OUT(i) (12582912 + (i) * 524288)

__device__ __forceinline__ float sigmoidf_fast(float x) {
    return __fdividef(1.f, 1.f + __expf(-x));
}
__device__ __forceinline__ float mp_siluf(float x) {
    return x * sigmoidf_fast(x) * GAIN;
}
__device__ __forceinline__ void st_split(bf16* h, bf16* l, long long i, float v) {
    bf16 hi = __float2bfloat16(v);
    h[i] = hi;
    l[i] = __float2bfloat16(v - __bfloat162float(hi));
}
__device__ __forceinline__ void st_split4(bf16* h, bf16* l, long long i,
                                          float a0, float a1, float a2, float a3) {
    union { bf16 b[4]; uint2 u; } H, L;
    H.b[0] = __float2bfloat16(a0); H.b[1] = __float2bfloat16(a1);
    H.b[2] = __float2bfloat16(a2); H.b[3] = __float2bfloat16(a3);
    L.b[0] = __float2bfloat16(a0 - __bfloat162float(H.b[0]));
    L.b[1] = __float2bfloat16(a1 - __bfloat162float(H.b[1]));
    L.b[2] = __float2bfloat16(a2 - __bfloat162float(H.b[2]));
    L.b[3] = __float2bfloat16(a3 - __bfloat162float(H.b[3]));
    *(uint2*)(h + i) = H.u;
    *(uint2*)(l + i) = L.u;
}
__device__ __forceinline__ void cpa16s(uint32_t saddr, const void* g) {
    asm volatile("cp.async.cg.shared.global [%0], [%1], 16;" :: "r"(saddr), "l"(g) : "memory");
}
__device__ __forceinline__ uint32_t smem_u32(const void* p) {
    uint32_t a;
    asm("{ .reg .u64 t; cvta.to.shared.u64 t, %1; cvt.u32.u64 %0, t; }" : "=r"(a) : "l"(p));
    return a;
}

/* ---------------- warp-MMA helpers (baseline PTX, sm_80+) --------------- */
__device__ __forceinline__ void ldm_x4(uint32_t& a0, uint32_t& a1, uint32_t& a2,
                                       uint32_t& a3, uint32_t addr) {
    asm volatile("ldmatrix.sync.aligned.m8n8.x4.shared.b16 {%0,%1,%2,%3}, [%4];"
                 : "=r"(a0), "=r"(a1), "=r"(a2), "=r"(a3) : "r"(addr));
}
__device__ __forceinline__ void ldm_x4t(uint32_t* r, uint32_t addr) {
    asm volatile("ldmatrix.sync.aligned.m8n8.x4.trans.shared.b16 {%0,%1,%2,%3}, [%4];"
                 : "=r"(r[0]), "=r"(r[1]), "=r"(r[2]), "=r"(r[3]) : "r"(addr));
}
__device__ __forceinline__ void mma16816(float* d, const uint32_t* a, uint32_t b0, uint32_t b1) {
    asm volatile("mma.sync.aligned.m16n8k16.row.col.f32.bf16.bf16.f32 "
                 "{%0,%1,%2,%3}, {%4,%5,%6,%7}, {%8,%9}, {%0,%1,%2,%3};"
                 : "+f"(d[0]), "+f"(d[1]), "+f"(d[2]), "+f"(d[3])
                 : "r"(a[0]), "r"(a[1]), "r"(a[2]), "r"(a[3]), "r"(b0), "r"(b1));
}

/* -------- fused weight normalization + bf16 split (segmented) ----------- */
struct NormSeg { const float* src; float* dstf; bf16* dsth; bf16* dstl;
                 int rowlen; int row_end; };
struct NormDescs { NormSeg s[16]; };

__global__ void norm_rows_multi(NormDescs d) {
    int blk = blockIdx.x;
    int seg = 0, row_start = 0;
#pragma unroll
    for (int i = 0; i < 16; i++) {
        if (blk >= d.s[i].row_end) { seg = i + 1; row_start = d.s[i].row_end; }
    }
    int r = blk - row_start;
    int rowlen = d.s[seg].rowlen;
    const float* s = d.s[seg].src + (long long)r * rowlen;
    float acc = 0.f;
    for (int i = threadIdx.x; i < rowlen; i += blockDim.x) { float v = s[i]; acc = fmaf(v, v, acc); }
#pragma unroll
    for (int off = 16; off; off >>= 1) acc += __shfl_down_sync(0xffffffffu, acc, off);
    __shared__ float sm[8];
    int warp = threadIdx.x >> 5, lane = threadIdx.x & 31;
    if (lane == 0) sm[warp] = acc;
    __syncthreads();
    if (threadIdx.x == 0) {
        float t = 0.f;
        int nw = blockDim.x >> 5;
        for (int i = 0; i < nw; i++) t += sm[i];
        sm[0] = rsqrtf(t + 1e-8f);
    }
    __syncthreads();
    float iv = sm[0];
    if (d.s[seg].dstf) {
        float* dst = d.s[seg].dstf + (long long)r * rowlen;
        for (int i = threadIdx.x; i < rowlen; i += blockDim.x) dst[i] = s[i] * iv;
    } else {
        bf16* h = d.s[seg].dsth + (long long)r * rowlen;
        bf16* l = d.s[seg].dstl + (long long)r * rowlen;
        for (int i = threadIdx.x; i < rowlen; i += blockDim.x) {
            float v = s[i] * iv;
            bf16 hi = __float2bfloat16(v);
            h[i] = hi;
            l[i] = __float2bfloat16(v - __bfloat162float(hi));
        }
    }
}

/* -------- pixel norm, 4 positions/thread (conv blocks) ------------------ */
template <bool SILU>
__global__ void pixelnorm4(const float* __restrict__ x, float* __restrict__ xn,
                           bf16* __restrict__ xh, bf16* __restrict__ xl,
                           int C, long long P, long long BP) {
    long long p = ((long long)blockIdx.x * blockDim.x + threadIdx.x) << 2;
    if (p >= BP) return;
    long long b = p / P, pp = p % P;
    const float* xi = x + b * (long long)C * P + pp;
    float s0 = 0.f, s1 = 0.f, s2 = 0.f, s3 = 0.f;
#pragma unroll 4
    for (int c = 0; c < C; c++) {
        float4 v = *(const float4*)(xi + (long long)c * P);
        s0 = fmaf(v.x, v.x, s0); s1 = fmaf(v.y, v.y, s1);
        s2 = fmaf(v.z, v.z, s2); s3 = fmaf(v.w, v.w, s3);
    }
    float ic = 1.f / (float)C;
    float iv0 = rsqrtf(s0 * ic + EPSN), iv1 = rsqrtf(s1 * ic + EPSN);
    float iv2 = rsqrtf(s2 * ic + EPSN), iv3 = rsqrtf(s3 * ic + EPSN);
    long long base = b * (long long)C * P + pp;
#pragma unroll 4
    for (int c = 0; c < C; c++) {
        long long o = base + (long long)c * P;
        float4 v = *(const float4*)(xi + (long long)c * P);
        float n0 = v.x * iv0, n1 = v.y * iv1, n2 = v.z * iv2, n3 = v.w * iv3;
        *(float4*)(xn + o) = make_float4(n0, n1, n2, n3);
        if (SILU) st_split4(xh, xl, o, mp_siluf(n0), mp_siluf(n1), mp_siluf(n2), mp_siluf(n3));
        else      st_split4(xh, xl, o, n0, n1, n2, n3);
    }
}

/* -------- pixel norm scalar (seq blocks, tiny) -------------------------- */
__global__ void pixelnorm_s(const float* __restrict__ x, float* __restrict__ xn,
                            bf16* __restrict__ xh, bf16* __restrict__ xl,
                            int C, long long P, long long BP) {
    long long p = (long long)blockIdx.x * blockDim.x + threadIdx.x;
    if (p >= BP) return;
    long long b = p / P, pp = p % P;
    const float* xi = x + b * (long long)C * P + pp;
    float s = 0.f;
#pragma unroll 8
    for (int c = 0; c < C; c++) { float v = xi[(long long)c * P]; s = fmaf(v, v, s); }
    float iv = rsqrtf(s / (float)C + EPSN);
    long long base = b * (long long)C * P + pp;
#pragma unroll 8
    for (int c = 0; c < C; c++) {
        float v = xi[(long long)c * P] * iv;
        long long o = base + (long long)c * P;
        xn[o] = v;
        st_split(xh, xl, o, v);
    }
}

/* -------- unified split-bf16 tensor GEMM, 3-stage pipeline -------------- */
/* RES: 0 none, 1 mp_add(R), 2 mp_add(recomputed proj residual),           */
/* 3 mp_add(R) + final mp_silu (writes network output)                     */
/* XGEN: X tile generated in-kernel from audio/pw/pb (block-0 c0w1)        */
template <int BM, int RES, bool XGEN>
__global__ void __launch_bounds__(256, 2) cgemm(
    const bf16* __restrict__ Wh, const bf16* __restrict__ Wl,
    const bf16* __restrict__ Xh, const bf16* __restrict__ Xl,
    float* __restrict__ Y, const float* __restrict__ R,
    const float* __restrict__ AU, const float* __restrict__ PW2,
    const float* __restrict__ PB2,
    int M, int K, long long P)
{
    constexpr int WPM = BM / 32;
    constexpr int WPP = 8 / WPM;
    constexpr int PW  = 128 / WPP;
    constexpr int NT  = PW / 8;
    constexpr int ASZ = BM * 64;
    constexpr int STG = 2 * ASZ + 16384;

    extern __shared__ __align__(128) char smraw[];
    const uint32_t smb = smem_u32(smraw);
    const int tid = threadIdx.x;
    const long long p0 = (long long)blockIdx.x * 128;
    const int m0 = blockIdx.y * BM;
    const int b = blockIdx.z;
    const int ntk = K >> 5;
    const int wid = tid >> 5, lane = tid & 31;
    const int wm = wid % WPM, wp = wid / WPM;

    /* proj moments (for XGEN tile gen and RES==2 epilogue) */
    float pm0 = 0.f, pm1 = 0.f, pm2 = 0.f;
    if (XGEN || RES == 2) {
#pragma unroll
        for (int i = 0; i < 64; i++) {
            float w = PW2[i], bb = PB2[i];
            pm0 = fmaf(w, w, pm0); pm1 = fmaf(w, bb, pm1); pm2 = fmaf(bb, bb, pm2);
        }
        pm0 *= (1.f / 64.f); pm1 *= (1.f / 64.f); pm2 *= (1.f / 64.f);
    }

    auto load_stage = [&](int kt, int s) {
#pragma unroll
        for (int g = 0; g < BM / 64; g++) {
            int r = (tid >> 2) + g * 64;
            int c = tid & 3;
            uint32_t off = (uint32_t)(r * 64 + ((c ^ ((r >> 1) & 3)) << 4));
            const bf16* wh = Wh + (long long)(m0 + r) * K + kt * 32 + c * 8;
            const bf16* wl = Wl + (long long)(m0 + r) * K + kt * 32 + c * 8;
            cpa16s(smb + s * STG + off, wh);
            cpa16s(smb + s * STG + ASZ + off, wl);
        }
        if (XGEN) {
            /* generate X tile: k row = channel, p from audio closed form */
            int r = tid >> 3;
            int cx = tid & 7;
            int kch = kt * 32 + r;
            float w = PW2[kch], bb = PB2[kch];
#pragma unroll
            for (int gg = 0; gg < 2; gg++) {
                int c = cx + gg * 8;
                long long pa = (long long)b * 262144LL + p0 + c * 8;
                float4 A0 = *(const float4*)(AU + pa);
                float4 A1 = *(const float4*)(AU + pa + 4);
                float Aa[8] = {A0.x, A0.y, A0.z, A0.w, A1.x, A1.y, A1.z, A1.w};
                union { bf16 e[8]; uint4 u; } Hh, Ll;
#pragma unroll
                for (int j = 0; j < 8; j++) {
                    float A = Aa[j];
                    float iv = rsqrtf(fmaf(A * A, pm0, fmaf(2.f * A, pm1, pm2)) + EPSN);
                    float v = mp_siluf(fmaf(A, w, bb) * iv);
                    bf16 hi = __float2bfloat16(v);
                    Hh.e[j] = hi;
                    Ll.e[j] = __float2bfloat16(v - __bfloat162float(hi));
                }
                uint32_t off = (uint32_t)(r * 256 + ((c ^ (r & 7)) << 4));
                *(uint4*)(smraw + s * STG + 2 * ASZ + off) = Hh.u;
                *(uint4*)(smraw + s * STG + 2 * ASZ + 8192 + off) = Ll.u;
            }
        } else {
            int r = tid >> 3;
            int cx = tid & 7;
#pragma unroll
            for (int gg = 0; gg < 2; gg++) {
                int c = cx + gg * 8;
                uint32_t off = (uint32_t)(r * 256 + ((c ^ (r & 7)) << 4));
                long long src = ((long long)b * K + kt * 32 + r) * P + p0 + c * 8;
                cpa16s(smb + s * STG + 2 * ASZ + off, Xh + src);
                cpa16s(smb + s * STG + 2 * ASZ + 8192 + off, Xl + src);
            }
        }
        asm volatile("cp.async.commit_group;" ::: "memory");
    };

    float acc[2][NT][4];
#pragma unroll
    for (int i = 0; i < 2; i++)
#pragma unroll
        for (int j = 0; j < NT; j++)
#pragma unroll
            for (int k = 0; k < 4; k++) acc[i][j][k] = 0.f;

    load_stage(0, 0);
    load_stage(1, 1);
    for (int kt = 0; kt < ntk; kt++) {
        const int s = kt % 3;
        if (kt + 1 < ntk) asm volatile("cp.async.wait_group 1;" ::: "memory");
        else              asm volatile("cp.async.wait_group 0;" ::: "memory");
        __syncthreads();
        if (kt + 2 < ntk) load_stage(kt + 2, (kt + 2) % 3);
        const uint32_t base = smb + s * STG;
#pragma unroll
        for (int ks = 0; ks < 2; ks++) {
            uint32_t bh[NT / 2][4], bl[NT / 2][4];
#pragma unroll
            for (int np = 0; np < NT / 2; np++) {
                int r = ks * 16 + (lane & 15);
                int chunk = wp * (PW / 8) + np * 2 + (lane >> 4);
                uint32_t ad = base + 2 * ASZ +
                              (uint32_t)(r * 256 + ((chunk ^ (r & 7)) << 4));
                ldm_x4t(bh[np], ad);
                ldm_x4t(bl[np], ad + 8192);
            }
#pragma unroll
            for (int mt = 0; mt < 2; mt++) {
                int r = wm * 32 + mt * 16 + (lane & 15);
                int chunk = ks * 2 + (lane >> 4);
                uint32_t ad = base + (uint32_t)(r * 64 + ((chunk ^ ((r >> 1) & 3)) << 4));
                uint32_t ah[4], al[4];
                ldm_x4(ah[0], ah[1], ah[2], ah[3], ad);
                ldm_x4(al[0], al[1], al[2], al[3], ad + ASZ);
#pragma unroll
                for (int np = 0; np < NT / 2; np++) {
                    mma16816(acc[mt][np * 2],     ah, bh[np][0], bh[np][1]);
                    mma16816(acc[mt][np * 2],     al, bh[np][0], bh[np][1]);
                    mma16816(acc[mt][np * 2],     ah, bl[np][0], bl[np][1]);
                    mma16816(acc[mt][np * 2 + 1], ah, bh[np][2], bh[np][3]);
                    mma16816(acc[mt][np * 2 + 1], al, bh[np][2], bh[np][3]);
                    mma16816(acc[mt][np * 2 + 1], ah, bl[np][2], bl[np][3]);
                }
            }
        }
    }

    const int qrow = lane >> 2;
    const int qcol = (lane & 3) << 1;
#pragma unroll
    for (int mt = 0; mt < 2; mt++) {
#pragma unroll
        for (int nt = 0; nt < NT; nt++) {
            int m = m0 + wm * 32 + mt * 16 + qrow;
            long long p = p0 + wp * PW + nt * 8 + qcol;
            long long o0 = ((long long)b * M + m) * P + p;
            long long o1 = ((long long)b * M + m + 8) * P + p;
            float2 v0 = make_float2(acc[mt][nt][0], acc[mt][nt][1]);
            float2 v1 = make_float2(acc[mt][nt][2], acc[mt][nt][3]);
            if (RES == 1 || RES == 3) {
                const float2 r0 = *(const float2*)(R + o0);
                const float2 r1 = *(const float2*)(R + o1);
                v0.x = fmaf(0.7f, r0.x, 0.3f * v0.x) * INV058;
                v0.y = fmaf(0.7f, r0.y, 0.3f * v0.y) * INV058;
                v1.x = fmaf(0.7f, r1.x, 0.3f * v1.x) * INV058;
                v1.y = fmaf(0.7f, r1.y, 0.3f * v1.y) * INV058;
            } else if (RES == 2) {
                float A0 = AU[(long long)b * 262144LL + p];
                float A1 = AU[(long long)b * 262144LL + p + 1];
                float iv0 = rsqrtf(fmaf(A0 * A0, pm0, fmaf(2.f * A0, pm1, pm2)) + EPSN);
                float iv1 = rsqrtf(fmaf(A1 * A1, pm0, fmaf(2.f * A1, pm1, pm2)) + EPSN);
                float w0 = PW2[m], b0v = PB2[m];
                float w1 = PW2[m + 8], b1v = PB2[m + 8];
                float r00 = fmaf(A0, w0, b0v) * iv0, r01 = fmaf(A1, w0, b0v) * iv1;
                float r10 = fmaf(A0, w1, b1v) * iv0, r11 = fmaf(A1, w1, b1v) * iv1;
                v0.x = fmaf(0.7f, r00, 0.3f * v0.x) * INV058;
                v0.y = fmaf(0.7f, r01, 0.3f * v0.y) * INV058;
                v1.x = fmaf(0.7f, r10, 0.3f * v1.x) * INV058;
                v1.y = fmaf(0.7f, r11, 0.3f * v1.y) * INV058;
            }
            if (RES == 3) {
                v0.x = mp_siluf(v0.x); v0.y = mp_siluf(v0.y);
                v1.x = mp_siluf(v1.x); v1.y = mp_siluf(v1.y);
            }
            *(float2*)(Y + o0) = v0;
            *(float2*)(Y + o1) = v1;
        }
    }
}

/* ------- depthwise 5x3 conv2d, 4 f-rows x 8 L-elems per thread ---------- */
__global__ void __launch_bounds__(256, 4) dwconv2d_silu(
                              const float* __restrict__ in, const float* __restrict__ w,
                              bf16* __restrict__ oh, bf16* __restrict__ ol,
                              int C, int F, long long total) {
    long long t = (long long)blockIdx.x * blockDim.x + threadIdx.x;
    if (t >= total) return;
    int l0 = (int)(t & 255) << 3;
    long long r = t >> 8;
    int Fq = F >> 2;
    int f0 = ((int)(r % Fq)) << 2; r /= Fq;
    int c = (int)(r % C);
    int b = (int)(r / C);
    const float* base = in + ((long long)(b * C + c)) * F * 2048LL;
    float wreg[15];
#pragma unroll
    for (int i = 0; i < 15; i++) wreg[i] = w[c * 15 + i];
    float a[4][8];
#pragma unroll
    for (int fo = 0; fo < 4; fo++)
#pragma unroll
        for (int j = 0; j < 8; j++) a[fo][j] = 0.f;
#pragma unroll
    for (int fi = 0; fi < 8; fi++) {
        int fr = f0 + fi - 2;
        if (fr < 0 || fr >= F) continue;
        const float* row = base + (long long)fr * 2048;
        float4 m0 = *(const float4*)(row + l0);
        float4 m1 = *(const float4*)(row + l0 + 4);
        float x[10];
        x[0] = (l0 > 0) ? row[l0 - 1] : 0.f;
        x[1] = m0.x; x[2] = m0.y; x[3] = m0.z; x[4] = m0.w;
        x[5] = m1.x; x[6] = m1.y; x[7] = m1.z; x[8] = m1.w;
        x[9] = (l0 + 8 < 2048) ? row[l0 + 8] : 0.f;
#pragma unroll
        for (int fo = 0; fo < 4; fo++) {
            int df = fi - fo;
            if (df < 0 || df > 4) continue;
            float w0 = wreg[df * 3 + 0], w1 = wreg[df * 3 + 1], w2 = wreg[df * 3 + 2];
#pragma unroll
            for (int j = 0; j < 8; j++)
                a[fo][j] = fmaf(w0, x[j], fmaf(w1, x[j + 1], fmaf(w2, x[j + 2], a[fo][j])));
        }
    }
#pragma unroll
    for (int fo = 0; fo < 4; fo++) {
        long long o = (((long long)(b * C + c)) * F + f0 + fo) * 2048LL + l0;
        st_split4(oh, ol, o,     mp_siluf(a[fo][0]), mp_siluf(a[fo][1]),
                                 mp_siluf(a[fo][2]), mp_siluf(a[fo][3]));
        st_split4(oh, ol, o + 4, mp_siluf(a[fo][4]), mp_siluf(a[fo][5]),
                                 mp_siluf(a[fo][6]), mp_siluf(a[fo][7]));
    }
}

/* ------- freq average pool, 4 elems/thread, packed stores --------------- */
__global__ void avgpool_f(const float* __restrict__ in, bf16* __restrict__ oh,
                          bf16* __restrict__ ol,
                          int C, int F, int Fo, int s, long long total4) {
    long long t = (long long)blockIdx.x * blockDim.x + threadIdx.x;
    if (t >= total4) return;
    long long e = t << 2;
    int l = (int)(e & 2047);
    long long r = e >> 11;
    int fo = (int)(r % Fo); r /= Fo;
    int c = (int)(r % C);
    int b = (int)(r / C);
    const float* p = in + (((long long)(b * C + c)) * F + fo * s) * 2048LL + l;
    float4 sum = make_float4(0.f, 0.f, 0.f, 0.f);
    for (int j = 0; j < s; j++) {
        float4 v = *(const float4*)(p + (long long)j * 2048);
        sum.x += v.x; sum.y += v.y; sum.z += v.z; sum.w += v.w;
    }
    float is = 1.f / (float)s;
    st_split4(oh, ol, e, sum.x * is, sum.y * is, sum.z * is, sum.w * is);
}

/* ------- seq depthwise k3, 8 elems/thread ------------------------------- */
__global__ void dwconv1d_silu(const float* __restrict__ hg, const float* __restrict__ w,
                              bf16* __restrict__ oh, bf16* __restrict__ ol) {
    long long t = (long long)blockIdx.x * blockDim.x + threadIdx.x;
    if (t >= 524288LL) return;
    int l0 = (int)(t & 255) << 3;
    int c = (int)((t >> 8) & 1023);
    int b = (int)(t >> 18);
    const float* row = hg + ((long long)b * 2048 + c) * 2048LL;
    const float* wc = w + c * 3;
    float4 m0 = *(const float4*)(row + l0);
    float4 m1 = *(const float4*)(row + l0 + 4);
    float x[10];
    x[0] = (l0 > 0) ? mp_siluf(row[l0 - 1]) : 0.f;
    x[1] = mp_siluf(m0.x); x[2] = mp_siluf(m0.y);
    x[3] = mp_siluf(m0.z); x[4] = mp_siluf(m0.w);
    x[5] = mp_siluf(m1.x); x[6] = mp_siluf(m1.y);
    x[7] = mp_siluf(m1.z); x[8] = mp_siluf(m1.w);
    x[9] = (l0 + 8 < 2048) ? mp_siluf(row[l0 + 8]) : 0.f;
    float w0 = wc[0], w1 = wc[1], w2 = wc[2];
    float a[8];
#pragma unroll
    for (int j = 0; j < 8; j++)
        a[j] = fmaf(w0, x[j], fmaf(w1, x[j + 1], w2 * x[j + 2]));
    long long o = ((long long)b * 1024 + c) * 2048LL + l0;
    st_split4(oh, ol, o,     mp_siluf(a[0]), mp_siluf(a[1]), mp_siluf(a[2]), mp_siluf(a[3]));
    st_split4(oh, ol, o + 4, mp_siluf(a[4]), mp_siluf(a[5]), mp_siluf(a[6]), mp_siluf(a[7]));
}

/* --------- minGRU blocked scan (4 elems/lane) + output gate ------------- */
__global__ void gru_scan(const float* __restrict__ u, const float* __restrict__ hg,
                         bf16* __restrict__ oh, bf16* __restrict__ ol) {
    int w = (int)((blockIdx.x * blockDim.x + threadIdx.x) >> 5);
    int lane = threadIdx.x & 31;
    if (w >= 2048) return;
    int bt = w >> 10, c = w & 1023;
    const float* zrow = u + ((long long)bt * 2048 + c) * 2048LL;
    const float* crow = zrow + 1024LL * 2048LL;
    const float* grow = hg + ((long long)bt * 2048 + 1024 + c) * 2048LL;
    long long obase = ((long long)bt * 1024 + c) * 2048LL;
    float carry = 0.f;
    for (int l0 = 0; l0 < 2048; l0 += 128) {
        int le = l0 + lane * 4;
        float4 zv = *(const float4*)(zrow + le);
        float4 cv = *(const float4*)(crow + le);
        float z0 = sigmoidf_fast(zv.x), z1 = sigmoidf_fast(zv.y);
        float z2 = sigmoidf_fast(zv.z), z3 = sigmoidf_fast(zv.w);
        float a0 = 1.f - z0, b0 = z0 * cv.x;
        float a1 = 1.f - z1, b1 = z1 * cv.y;
        float a2 = 1.f - z2, b2 = z2 * cv.z;
        float a3 = 1.f - z3, b3 = z3 * cv.w;
        float A = a0, B = b0;
        A = a1 * A; B = fmaf(a1, B, b1);
        A = a2 * A; B = fmaf(a2, B, b2);
        A = a3 * A; B = fmaf(a3, B, b3);
        float As = A, Bs = B;
#pragma unroll
        for (int off = 1; off < 32; off <<= 1) {
            float Ap = __shfl_up_sync(0xffffffffu, As, off);
            float Bp = __shfl_up_sync(0xffffffffu, Bs, off);
            if (lane >= off) { Bs = fmaf(As, Bp, Bs); As *= Ap; }
        }
        float Ae = __shfl_up_sync(0xffffffffu, As, 1);
        float Be = __shfl_up_sync(0xffffffffu, Bs, 1);
        if (lane == 0) { Ae = 1.f; Be = 0.f; }
        float hprev = fmaf(Ae, carry, Be);
        float h0 = fmaf(a0, hprev, b0);
        float h1 = fmaf(a1, h0, b1);
        float h2 = fmaf(a2, h1, b2);
        float h3 = fmaf(a3, h2, b3);
        carry = __shfl_sync(0xffffffffu, fmaf(As, carry, Bs), 31);
        float4 gv = *(const float4*)(grow + le);
        st_split4(oh, ol, obase + le,
                  h0 * mp_siluf(gv.x), h1 * mp_siluf(gv.y),
                  h2 * mp_siluf(gv.z), h3 * mp_siluf(gv.w));
    }
}

/* ======================================================================== */
extern "C" void kernel_launch(void* const* d_in, const int* in_sizes, int n_in,
                              void* d_out, int out_size) {
    const float* audio = (const float*)d_in[0];
    const float* pw    = (const float*)d_in[1];
    const float* pb    = (const float*)d_in[2];
    const float* c0w1  = (const float*)d_in[3];
    const float* c0wd  = (const float*)d_in[4];
    const float* c0w2  = (const float*)d_in[5];
    const float* c0dn  = (const float*)d_in[6];
    const float* c1w1  = (const float*)d_in[7];
    const float* c1wd  = (const float*)d_in[8];
    const float* c1w2  = (const float*)d_in[9];
    const float* c1dn  = (const float*)d_in[10];
    const float* c2w1  = (const float*)d_in[11];
    const float* c2wd  = (const float*)d_in[12];
    const float* c2w2  = (const float*)d_in[13];
    const float* c2dn  = (const float*)d_in[14];
    const float* hgw   = (const float*)d_in[15];
    const float* dww   = (const float*)d_in[16];
    const float* gruw  = (const float*)d_in[17];
    const float* outw  = (const float*)d_in[18];

    float *wp, *xn, *xsf, *bufA, *bufBf, *hb, *poolf, *xb;
    bf16 *wbf, *cw;
    cudaGetSymbolAddress((void**)&wp,    g_wpool);
    cudaGetSymbolAddress((void**)&xn,    g_xn);
    cudaGetSymbolAddress((void**)&xsf,   g_xs);
    cudaGetSymbolAddress((void**)&bufA,  g_bufA);
    cudaGetSymbolAddress((void**)&bufBf, g_bufB);
    cudaGetSymbolAddress((void**)&hb,    g_h);
    cudaGetSymbolAddress((void**)&poolf, g_pool);
    cudaGetSymbolAddress((void**)&xb,    g_x);
    cudaGetSymbolAddress((void**)&wbf,   g_wbf);
    cudaGetSymbolAddress((void**)&cw,    g_cwbf);

    bf16* xs   = (bf16*)xsf;
    bf16* bufB = (bf16*)bufBf;
    bf16* pool = (bf16*)poolf;
    const float* NUL = (const float*)0;
    const bf16* NULB = (const bf16*)0;

    cudaFuncSetAttribute(cgemm<128, 0, false>, cudaFuncAttributeMaxDynamicSharedMemorySize, 98304);
    cudaFuncSetAttribute(cgemm<128, 0, true>,  cudaFuncAttributeMaxDynamicSharedMemorySize, 98304);
    cudaFuncSetAttribute(cgemm<128, 1, false>, cudaFuncAttributeMaxDynamicSharedMemorySize, 98304);
    cudaFuncSetAttribute(cgemm<128, 3, false>, cudaFuncAttributeMaxDynamicSharedMemorySize, 98304);
    cudaFuncSetAttribute(cgemm<64, 2, false>,  cudaFuncAttributeMaxDynamicSharedMemorySize, 73728);

    /* fused weight normalization + bf16 split: one launch for all 16 */
    NormDescs nd;
    {
        const float* srcs[16] = {c0w1, c0wd, c0w2, c0dn, c1w1, c1wd, c1w2, c1dn,
                                 c2w1, c2wd, c2w2, c2dn, hgw, dww, gruw, outw};
        int rows[16]   = {128, 128, 64, 128, 256, 256, 128, 256, 512, 512, 256, 512,
                          8192, 4096, 8192, 2048};
        int rowlen[16] = {64, 15, 128, 64, 128, 15, 256, 128, 256, 15, 512, 256,
                          512, 3, 1024, 1024};
        float* dstf[16] = {0, wp + O_C0WD, 0, 0, 0, wp + O_C1WD, 0, 0,
                           0, wp + O_C2WD, 0, 0, 0, wp + O_DW, 0, 0};
        int hofs[16] = {CWH_C0W1, -1, CWH_C0W2, CWH_C0DN, CWH_C1W1, -1, CWH_C1W2,
                        CWH_C1DN, CWH_C2W1, -1, CWH_C2W2, CWH_C2DN, -1, -1, -1, -1};
        int acc = 0;
        for (int i = 0; i < 16; i++) {
            acc += rows[i];
            nd.s[i].src = srcs[i];
            nd.s[i].dstf = dstf[i];
            nd.s[i].rowlen = rowlen[i];
            nd.s[i].row_end = acc;
            if (dstf[i]) { nd.s[i].dsth = 0; nd.s[i].dstl = 0; }
            else if (hofs[i] >= 0) { nd.s[i].dsth = cw + hofs[i]; nd.s[i].dstl = cw + hofs[i] + CWLO; }
        }
        nd.s[12].dsth = wbf + WH_HG(0);  nd.s[12].dstl = wbf + WH_HG(0) + WLO;
        nd.s[14].dsth = wbf + WH_GRU(0); nd.s[14].dstl = wbf + WH_GRU(0) + WLO;
        nd.s[15].dsth = wbf + WH_OUT(0); nd.s[15].dstl = wbf + WH_OUT(0) + WLO;
        norm_rows_multi<<<acc, 128>>>(nd);
    }

    /* block 0  (C 64->128->64->pool4->128, F=128, P=262144)
       c0w1 generates its X tile from audio in-kernel (XGEN) */
    cgemm<128, 0, true><<<dim3(2048, 1, 2), 256, 98304>>>(cw + CWH_C0W1, cw + CWH_C0W1 + CWLO,
        NULB, NULB, bufA, NUL, audio, pw, pb, 128, 64, 262144LL);
    dwconv2d_silu<<<8192, 256>>>(bufA, wp + O_C0WD, bufB, bufB + BUFB_LO, 128, 128, 2097152LL);
    cgemm<64, 2, false><<<dim3(2048, 1, 2), 256, 73728>>>(cw + CWH_C0W2, cw + CWH_C0W2 + CWLO,
        bufB, bufB + BUFB_LO, hb, NUL, audio, pw, pb, 64, 128, 262144LL);
    avgpool_f<<<8192, 256>>>(hb, pool, pool + POOL_LO, 64, 128, 32, 4, 2097152LL);
    cgemm<128, 0, false><<<dim3(512, 1, 2), 256, 98304>>>(cw + CWH_C0DN, cw + CWH_C0DN + CWLO,
        pool, pool + POOL_LO, xb, NUL, NUL, NUL, NUL, 128, 64, 65536LL);

    /* block 1  (C 128->256->128->pool4->256, F=32, P=65536) */
    pixelnorm4<true><<<128, 256>>>(xb, xn, xs, xs + XS_LO, 128, 65536LL, 131072LL);
    cgemm<128, 0, false><<<dim3(512, 2, 2), 256, 98304>>>(cw + CWH_C1W1, cw + CWH_C1W1 + CWLO,
        xs, xs + XS_LO, bufA, NUL, NUL, NUL, NUL, 256, 128, 65536LL);
    dwconv2d_silu<<<4096, 256>>>(bufA, wp + O_C1WD, bufB, bufB + BUFB_LO, 256, 32, 1048576LL);
    cgemm<128, 1, false><<<dim3(512, 1, 2), 256, 98304>>>(cw + CWH_C1W2, cw + CWH_C1W2 + CWLO,
        bufB, bufB + BUFB_LO, hb, xn, NUL, NUL, NUL, 128, 256, 65536LL);
    avgpool_f<<<4096, 256>>>(hb, pool, pool + POOL_LO, 128, 32, 8, 4, 1048576LL);
    cgemm<128, 0, false><<<dim3(128, 2, 2), 256, 98304>>>(cw + CWH_C1DN, cw + CWH_C1DN + CWLO,
        pool, pool + POOL_LO, xb, NUL, NUL, NUL, NUL, 256, 128, 16384LL);

    /* block 2  (C 256->512->256->pool8->512, F=8, P=16384) */
    pixelnorm4<true><<<32, 256>>>(xb, xn, xs, xs + XS_LO, 256, 16384LL, 32768LL);
    cgemm<128, 0, false><<<dim3(128, 4, 2), 256, 98304>>>(cw + CWH_C2W1, cw + CWH_C2W1 + CWLO,
        xs, xs + XS_LO, bufA, NUL, NUL, NUL, NUL, 512, 256, 16384LL);
    dwconv2d_silu<<<2048, 256>>>(bufA, wp + O_C2WD, bufB, bufB + BUFB_LO, 512, 8, 524288LL);
    cgemm<128, 1, false><<<dim3(128, 2, 2), 256, 98304>>>(cw + CWH_C2W2, cw + CWH_C2W2 + CWLO,
        bufB, bufB + BUFB_LO, hb, xn, NUL, NUL, NUL, 256, 512, 16384LL);
    avgpool_f<<<1024, 256>>>(hb, pool, pool + POOL_LO, 256, 8, 1, 8, 262144LL);
    cgemm<128, 0, false><<<dim3(16, 4, 2), 256, 98304>>>(cw + CWH_C2DN, cw + CWH_C2DN + CWLO,
        pool, pool + POOL_LO, xb, NUL, NUL, NUL, NUL, 512, 256, 2048LL);

    /* seq blocks ×4  (C=512, L=2048); last out-GEMM fuses final silu */
    for (int i = 0; i < 4; i++) {
        pixelnorm_s<<<128, 32>>>(xb, xn, xs, xs + XS_LO, 512, 2048LL, 4096LL);
        cgemm<128, 0, false><<<dim3(16, 16, 2), 256, 98304>>>(
            wbf + WH_HG(i), wbf + WH_HG(i) + WLO, xs, xs + XS_LO,
            bufA, NUL, NUL, NUL, NUL, 2048, 512, 2048LL);
        dwconv1d_silu<<<2048, 256>>>(bufA, wp + O_DW + i * 3072, bufB, bufB + BUFB_LO);
        cgemm<128, 0, false><<<dim3(16, 16, 2), 256, 98304>>>(
            wbf + WH_GRU(i), wbf + WH_GRU(i) + WLO, bufB, bufB + BUFB_LO,
            hb, NUL, NUL, NUL, NUL, 2048, 1024, 2048LL);
        gru_scan<<<256, 256>>>(hb, bufA, pool, pool + POOL_LO);
        if (i < 3) {
            cgemm<128, 1, false><<<dim3(16, 4, 2), 256, 98304>>>(
                wbf + WH_OUT(i), wbf + WH_OUT(i) + WLO, pool, pool + POOL_LO,
                xb, xn, NUL, NUL, NUL, 512, 1024, 2048LL);
        } else {
            cgemm<128, 3, false><<<dim3(16, 4, 2), 256, 98304>>>(
                wbf + WH_OUT(i), wbf + WH_OUT(i) + WLO, pool, pool + POOL_LO,
                (float*)d_out, xn, NUL, NUL, NUL, 512, 1024, 2048LL);
        }
    }
}

// round 17
// speedup vs baseline: 1.0271x; 1.0271x over previous
#include <cuda_runtime.h>
#include <cuda_bf16.h>
#include <cstdint>

#define GAIN   1.6778523489932886f   /* 1/0.596 */
#define INV058 1.3130643285972254f   /* 1/sqrt(0.7^2+0.3^2) */
#define EPSN   1e-4f

typedef unsigned long long ull;
typedef __nv_bfloat16 bf16;

/* ---------------- static device scratch (no allocations allowed) -------- */
__device__ __align__(16) float g_wpool[15230976];
__device__ __align__(16) float g_xn[33554432];
__device__ __align__(16) float g_xs[33554432];    /* bf16 planes: hi | lo   */
__device__ __align__(16) float g_bufA[67108864];
__device__ __align__(16) float g_bufB[67108864];  /* bf16 planes            */
__device__ __align__(16) float g_h[33554432];
__device__ __align__(16) float g_pool[8388608];   /* bf16 planes            */
__device__ __align__(16) float g_x[16777216];
__device__ __align__(16) bf16 g_wbf[29360128];    /* seq weights: hi | lo   */
__device__ __align__(16) bf16 g_cwbf[1048576];    /* conv weights: hi | lo  */

#define XS_LO   33554432
#define BUFB_LO 67108864
#define POOL_LO 8388608

/* fp32 weight pool offsets (depthwise weights only) */
#define O_C0WD 8192
#define O_C1WD 59264
#define O_C2WD 259712
#define O_DW   4723840

/* bf16 conv-weight hi offsets in g_cwbf; lo at +CWLO */
#define CWLO 516096
#define CWH_C0W1 0
#define CWH_C0W2 8192
#define CWH_C0DN 16384
#define CWH_C1W1 24576
#define CWH_C1W2 57344
#define CWH_C1DN 90112
#define CWH_C2W1 122880
#define CWH_C2W2 253952
#define CWH_C2DN 385024

/* bf16 seq-weight hi offsets in g_wbf; lo at +WLO */
#define WLO 14680064
#define WH_HG(i)  ((i) * 1048576)
#define WH_GRU(i) (4194304 + (i) * 2097152)
#define WH_OUT(i) (12582912 + (i) * 524288)

__device__ __forceinline__ float sigmoidf_fast(float x) {
    return __fdividef(1.f, 1.f + __expf(-x));
}
__device__ __forceinline__ float mp_siluf(float x) {
    return x * sigmoidf_fast(x) * GAIN;
}
__device__ __forceinline__ void st_split(bf16* h, bf16* l, long long i, float v) {
    bf16 hi = __float2bfloat16(v);
    h[i] = hi;
    l[i] = __float2bfloat16(v - __bfloat162float(hi));
}
__device__ __forceinline__ void st_split4(bf16* h, bf16* l, long long i,
                                          float a0, float a1, float a2, float a3) {
    union { bf16 b[4]; uint2 u; } H, L;
    H.b[0] = __float2bfloat16(a0); H.b[1] = __float2bfloat16(a1);
    H.b[2] = __float2bfloat16(a2); H.b[3] = __float2bfloat16(a3);
    L.b[0] = __float2bfloat16(a0 - __bfloat162float(H.b[0]));
    L.b[1] = __float2bfloat16(a1 - __bfloat162float(H.b[1]));
    L.b[2] = __float2bfloat16(a2 - __bfloat162float(H.b[2]));
    L.b[3] = __float2bfloat16(a3 - __bfloat162float(H.b[3]));
    *(uint2*)(h + i) = H.u;
    *(uint2*)(l + i) = L.u;
}
__device__ __forceinline__ void cpa16s(uint32_t saddr, const void* g) {
    asm volatile("cp.async.cg.shared.global [%0], [%1], 16;" :: "r"(saddr), "l"(g) : "memory");
}
__device__ __forceinline__ uint32_t smem_u32(const void* p) {
    uint32_t a;
    asm("{ .reg .u64 t; cvta.to.shared.u64 t, %1; cvt.u32.u64 %0, t; }" : "=r"(a) : "l"(p));
    return a;
}

/* ---------------- warp-MMA helpers (baseline PTX, sm_80+) --------------- */
__device__ __forceinline__ void ldm_x4(uint32_t& a0, uint32_t& a1, uint32_t& a2,
                                       uint32_t& a3, uint32_t addr) {
    asm volatile("ldmatrix.sync.aligned.m8n8.x4.shared.b16 {%0,%1,%2,%3}, [%4];"
                 : "=r"(a0), "=r"(a1), "=r"(a2), "=r"(a3) : "r"(addr));
}
__device__ __forceinline__ void ldm_x4t(uint32_t* r, uint32_t addr) {
    asm volatile("ldmatrix.sync.aligned.m8n8.x4.trans.shared.b16 {%0,%1,%2,%3}, [%4];"
                 : "=r"(r[0]), "=r"(r[1]), "=r"(r[2]), "=r"(r[3]) : "r"(addr));
}
__device__ __forceinline__ void mma16816(float* d, const uint32_t* a, uint32_t b0, uint32_t b1) {
    asm volatile("mma.sync.aligned.m16n8k16.row.col.f32.bf16.bf16.f32 "
                 "{%0,%1,%2,%3}, {%4,%5,%6,%7}, {%8,%9}, {%0,%1,%2,%3};"
                 : "+f"(d[0]), "+f"(d[1]), "+f"(d[2]), "+f"(d[3])
                 : "r"(a[0]), "r"(a[1]), "r"(a[2]), "r"(a[3]), "r"(b0), "r"(b1));
}

/* -------- fused weight normalization + bf16 split (segmented) ----------- */
struct NormSeg { const float* src; float* dstf; bf16* dsth; bf16* dstl;
                 int rowlen; int row_end; };
struct NormDescs { NormSeg s[16]; };

__global__ void norm_rows_multi(NormDescs d) {
    int blk = blockIdx.x;
    int seg = 0, row_start = 0;
#pragma unroll
    for (int i = 0; i < 16; i++) {
        if (blk >= d.s[i].row_end) { seg = i + 1; row_start = d.s[i].row_end; }
    }
    int r = blk - row_start;
    int rowlen = d.s[seg].rowlen;
    const float* s = d.s[seg].src + (long long)r * rowlen;
    float acc = 0.f;
    for (int i = threadIdx.x; i < rowlen; i += blockDim.x) { float v = s[i]; acc = fmaf(v, v, acc); }
#pragma unroll
    for (int off = 16; off; off >>= 1) acc += __shfl_down_sync(0xffffffffu, acc, off);
    __shared__ float sm[8];
    int warp = threadIdx.x >> 5, lane = threadIdx.x & 31;
    if (lane == 0) sm[warp] = acc;
    __syncthreads();
    if (threadIdx.x == 0) {
        float t = 0.f;
        int nw = blockDim.x >> 5;
        for (int i = 0; i < nw; i++) t += sm[i];
        sm[0] = rsqrtf(t + 1e-8f);
    }
    __syncthreads();
    float iv = sm[0];
    if (d.s[seg].dstf) {
        float* dst = d.s[seg].dstf + (long long)r * rowlen;
        for (int i = threadIdx.x; i < rowlen; i += blockDim.x) dst[i] = s[i] * iv;
    } else {
        bf16* h = d.s[seg].dsth + (long long)r * rowlen;
        bf16* l = d.s[seg].dstl + (long long)r * rowlen;
        for (int i = threadIdx.x; i < rowlen; i += blockDim.x) {
            float v = s[i] * iv;
            bf16 hi = __float2bfloat16(v);
            h[i] = hi;
            l[i] = __float2bfloat16(v - __bfloat162float(hi));
        }
    }
}

/* -------- proj pixel norm, 4 positions/thread, packed stores ------------ */
__global__ void proj_pixelnorm(const float* __restrict__ audio, const float* __restrict__ pw,
                               const float* __restrict__ pb,
                               bf16* __restrict__ xh, bf16* __restrict__ xl) {
    long long p = ((long long)blockIdx.x * blockDim.x + threadIdx.x) << 2;
    if (p >= 524288LL) return;
    float pm0 = 0.f, pm1 = 0.f, pm2 = 0.f;
#pragma unroll
    for (int i = 0; i < 64; i++) {
        float w = pw[i], bb = pb[i];
        pm0 = fmaf(w, w, pm0); pm1 = fmaf(w, bb, pm1); pm2 = fmaf(bb, bb, pm2);
    }
    pm0 *= (1.f / 64.f); pm1 *= (1.f / 64.f); pm2 *= (1.f / 64.f);
    float4 A = *(const float4*)(audio + p);
    float iv0 = rsqrtf(fmaf(A.x * A.x, pm0, fmaf(2.f * A.x, pm1, pm2)) + EPSN);
    float iv1 = rsqrtf(fmaf(A.y * A.y, pm0, fmaf(2.f * A.y, pm1, pm2)) + EPSN);
    float iv2 = rsqrtf(fmaf(A.z * A.z, pm0, fmaf(2.f * A.z, pm1, pm2)) + EPSN);
    float iv3 = rsqrtf(fmaf(A.w * A.w, pm0, fmaf(2.f * A.w, pm1, pm2)) + EPSN);
    long long b = p >> 18;
    long long rem = p & 262143LL;
    long long base = b * 64LL * 262144LL + rem;
#pragma unroll
    for (int c = 0; c < 64; c++) {
        float w = pw[c], bb = pb[c];
        st_split4(xh, xl, base + (long long)c * 262144LL,
                  mp_siluf(fmaf(A.x, w, bb) * iv0), mp_siluf(fmaf(A.y, w, bb) * iv1),
                  mp_siluf(fmaf(A.z, w, bb) * iv2), mp_siluf(fmaf(A.w, w, bb) * iv3));
    }
}

/* -------- pixel norm, 4 positions/thread (conv blocks) ------------------ */
template <bool SILU>
__global__ void pixelnorm4(const float* __restrict__ x, float* __restrict__ xn,
                           bf16* __restrict__ xh, bf16* __restrict__ xl,
                           int C, long long P, long long BP) {
    long long p = ((long long)blockIdx.x * blockDim.x + threadIdx.x) << 2;
    if (p >= BP) return;
    long long b = p / P, pp = p % P;
    const float* xi = x + b * (long long)C * P + pp;
    float s0 = 0.f, s1 = 0.f, s2 = 0.f, s3 = 0.f;
#pragma unroll 4
    for (int c = 0; c < C; c++) {
        float4 v = *(const float4*)(xi + (long long)c * P);
        s0 = fmaf(v.x, v.x, s0); s1 = fmaf(v.y, v.y, s1);
        s2 = fmaf(v.z, v.z, s2); s3 = fmaf(v.w, v.w, s3);
    }
    float ic = 1.f / (float)C;
    float iv0 = rsqrtf(s0 * ic + EPSN), iv1 = rsqrtf(s1 * ic + EPSN);
    float iv2 = rsqrtf(s2 * ic + EPSN), iv3 = rsqrtf(s3 * ic + EPSN);
    long long base = b * (long long)C * P + pp;
#pragma unroll 4
    for (int c = 0; c < C; c++) {
        long long o = base + (long long)c * P;
        float4 v = *(const float4*)(xi + (long long)c * P);
        float n0 = v.x * iv0, n1 = v.y * iv1, n2 = v.z * iv2, n3 = v.w * iv3;
        *(float4*)(xn + o) = make_float4(n0, n1, n2, n3);
        if (SILU) st_split4(xh, xl, o, mp_siluf(n0), mp_siluf(n1), mp_siluf(n2), mp_siluf(n3));
        else      st_split4(xh, xl, o, n0, n1, n2, n3);
    }
}

/* -------- pixel norm scalar (seq blocks, tiny) -------------------------- */
__global__ void pixelnorm_s(const float* __restrict__ x, float* __restrict__ xn,
                            bf16* __restrict__ xh, bf16* __restrict__ xl,
                            int C, long long P, long long BP) {
    long long p = (long long)blockIdx.x * blockDim.x + threadIdx.x;
    if (p >= BP) return;
    long long b = p / P, pp = p % P;
    const float* xi = x + b * (long long)C * P + pp;
    float s = 0.f;
#pragma unroll 8
    for (int c = 0; c < C; c++) { float v = xi[(long long)c * P]; s = fmaf(v, v, s); }
    float iv = rsqrtf(s / (float)C + EPSN);
    long long base = b * (long long)C * P + pp;
#pragma unroll 8
    for (int c = 0; c < C; c++) {
        float v = xi[(long long)c * P] * iv;
        long long o = base + (long long)c * P;
        xn[o] = v;
        st_split(xh, xl, o, v);
    }
}

/* -------- unified split-bf16 tensor GEMM, 3-stage pipeline -------------- */
/* RES: 0 none, 1 mp_add(R), 2 mp_add(recomputed proj residual),           */
/* 3 mp_add(R) + final mp_silu (writes network output)                     */
template <int BM, int RES>
__global__ void __launch_bounds__(256, 2) cgemm(
    const bf16* __restrict__ Wh, const bf16* __restrict__ Wl,
    const bf16* __restrict__ Xh, const bf16* __restrict__ Xl,
    float* __restrict__ Y, const float* __restrict__ R,
    const float* __restrict__ AU, const float* __restrict__ PW2,
    const float* __restrict__ PB2,
    int M, int K, long long P)
{
    constexpr int WPM = BM / 32;
    constexpr int WPP = 8 / WPM;
    constexpr int PW  = 128 / WPP;
    constexpr int NT  = PW / 8;
    constexpr int ASZ = BM * 64;
    constexpr int STG = 2 * ASZ + 16384;

    extern __shared__ __align__(128) char smraw[];
    const uint32_t smb = smem_u32(smraw);
    const int tid = threadIdx.x;
    const long long p0 = (long long)blockIdx.x * 128;
    const int m0 = blockIdx.y * BM;
    const int b = blockIdx.z;
    const int ntk = K >> 5;
    const int wid = tid >> 5, lane = tid & 31;
    const int wm = wid % WPM, wp = wid / WPM;

    auto load_stage = [&](int kt, int s) {
        uint32_t base = smb + s * STG;
#pragma unroll
        for (int g = 0; g < BM / 64; g++) {
            int r = (tid >> 2) + g * 64;
            int c = tid & 3;
            uint32_t off = (uint32_t)(r * 64 + ((c ^ ((r >> 1) & 3)) << 4));
            const bf16* wh = Wh + (long long)(m0 + r) * K + kt * 32 + c * 8;
            const bf16* wl = Wl + (long long)(m0 + r) * K + kt * 32 + c * 8;
            cpa16s(base + off, wh);
            cpa16s(base + ASZ + off, wl);
        }
        {
            int r = tid >> 3;
            int cx = tid & 7;
#pragma unroll
            for (int gg = 0; gg < 2; gg++) {
                int c = cx + gg * 8;
                uint32_t off = (uint32_t)(r * 256 + ((c ^ (r & 7)) << 4));
                long long src = ((long long)b * K + kt * 32 + r) * P + p0 + c * 8;
                cpa16s(base + 2 * ASZ + off, Xh + src);
                cpa16s(base + 2 * ASZ + 8192 + off, Xl + src);
            }
        }
        asm volatile("cp.async.commit_group;" ::: "memory");
    };

    float acc[2][NT][4];
#pragma unroll
    for (int i = 0; i < 2; i++)
#pragma unroll
        for (int j = 0; j < NT; j++)
#pragma unroll
            for (int k = 0; k < 4; k++) acc[i][j][k] = 0.f;

    load_stage(0, 0);
    load_stage(1, 1);
    for (int kt = 0; kt < ntk; kt++) {
        const int s = kt % 3;
        if (kt + 1 < ntk) asm volatile("cp.async.wait_group 1;" ::: "memory");
        else              asm volatile("cp.async.wait_group 0;" ::: "memory");
        __syncthreads();
        if (kt + 2 < ntk) load_stage(kt + 2, (kt + 2) % 3);
        const uint32_t base = smb + s * STG;
#pragma unroll
        for (int ks = 0; ks < 2; ks++) {
            uint32_t bh[NT / 2][4], bl[NT / 2][4];
#pragma unroll
            for (int np = 0; np < NT / 2; np++) {
                int r = ks * 16 + (lane & 15);
                int chunk = wp * (PW / 8) + np * 2 + (lane >> 4);
                uint32_t ad = base + 2 * ASZ +
                              (uint32_t)(r * 256 + ((chunk ^ (r & 7)) << 4));
                ldm_x4t(bh[np], ad);
                ldm_x4t(bl[np], ad + 8192);
            }
#pragma unroll
            for (int mt = 0; mt < 2; mt++) {
                int r = wm * 32 + mt * 16 + (lane & 15);
                int chunk = ks * 2 + (lane >> 4);
                uint32_t ad = base + (uint32_t)(r * 64 + ((chunk ^ ((r >> 1) & 3)) << 4));
                uint32_t ah[4], al[4];
                ldm_x4(ah[0], ah[1], ah[2], ah[3], ad);
                ldm_x4(al[0], al[1], al[2], al[3], ad + ASZ);
#pragma unroll
                for (int np = 0; np < NT / 2; np++) {
                    mma16816(acc[mt][np * 2],     ah, bh[np][0], bh[np][1]);
                    mma16816(acc[mt][np * 2],     al, bh[np][0], bh[np][1]);
                    mma16816(acc[mt][np * 2],     ah, bl[np][0], bl[np][1]);
                    mma16816(acc[mt][np * 2 + 1], ah, bh[np][2], bh[np][3]);
                    mma16816(acc[mt][np * 2 + 1], al, bh[np][2], bh[np][3]);
                    mma16816(acc[mt][np * 2 + 1], ah, bl[np][2], bl[np][3]);
                }
            }
        }
    }

    float pm0 = 0.f, pm1 = 0.f, pm2 = 0.f;
    if (RES == 2) {
#pragma unroll
        for (int i = 0; i < 64; i++) {
            float w = PW2[i], bb = PB2[i];
            pm0 = fmaf(w, w, pm0); pm1 = fmaf(w, bb, pm1); pm2 = fmaf(bb, bb, pm2);
        }
        pm0 *= (1.f / 64.f); pm1 *= (1.f / 64.f); pm2 *= (1.f / 64.f);
    }

    const int qrow = lane >> 2;
    const int qcol = (lane & 3) << 1;
#pragma unroll
    for (int mt = 0; mt < 2; mt++) {
#pragma unroll
        for (int nt = 0; nt < NT; nt++) {
            int m = m0 + wm * 32 + mt * 16 + qrow;
            long long p = p0 + wp * PW + nt * 8 + qcol;
            long long o0 = ((long long)b * M + m) * P + p;
            long long o1 = ((long long)b * M + m + 8) * P + p;
            float2 v0 = make_float2(acc[mt][nt][0], acc[mt][nt][1]);
            float2 v1 = make_float2(acc[mt][nt][2], acc[mt][nt][3]);
            if (RES == 1 || RES == 3) {
                const float2 r0 = *(const float2*)(R + o0);
                const float2 r1 = *(const float2*)(R + o1);
                v0.x = fmaf(0.7f, r0.x, 0.3f * v0.x) * INV058;
                v0.y = fmaf(0.7f, r0.y, 0.3f * v0.y) * INV058;
                v1.x = fmaf(0.7f, r1.x, 0.3f * v1.x) * INV058;
                v1.y = fmaf(0.7f, r1.y, 0.3f * v1.y) * INV058;
            } else if (RES == 2) {
                float A0 = AU[(long long)b * 262144LL + p];
                float A1 = AU[(long long)b * 262144LL + p + 1];
                float iv0 = rsqrtf(fmaf(A0 * A0, pm0, fmaf(2.f * A0, pm1, pm2)) + EPSN);
                float iv1 = rsqrtf(fmaf(A1 * A1, pm0, fmaf(2.f * A1, pm1, pm2)) + EPSN);
                float w0 = PW2[m], b0v = PB2[m];
                float w1 = PW2[m + 8], b1v = PB2[m + 8];
                float r00 = fmaf(A0, w0, b0v) * iv0, r01 = fmaf(A1, w0, b0v) * iv1;
                float r10 = fmaf(A0, w1, b1v) * iv0, r11 = fmaf(A1, w1, b1v) * iv1;
                v0.x = fmaf(0.7f, r00, 0.3f * v0.x) * INV058;
                v0.y = fmaf(0.7f, r01, 0.3f * v0.y) * INV058;
                v1.x = fmaf(0.7f, r10, 0.3f * v1.x) * INV058;
                v1.y = fmaf(0.7f, r11, 0.3f * v1.y) * INV058;
            }
            if (RES == 3) {
                v0.x = mp_siluf(v0.x); v0.y = mp_siluf(v0.y);
                v1.x = mp_siluf(v1.x); v1.y = mp_siluf(v1.y);
            }
            *(float2*)(Y + o0) = v0;
            *(float2*)(Y + o1) = v1;
        }
    }
}

/* ------- depthwise 5x3 conv2d, smem-tiled: 1x gmem reads ---------------- */
/* Block owns one (b,c) and an LT-wide L-tile across all F rows.           */
/* F*LT == 8192; 256 threads; each computes a 4(f) x 8(L) patch.           */
template <int F, int LT>
__global__ void dwconv2d_silu_t(const float* __restrict__ in, const float* __restrict__ w,
                                bf16* __restrict__ oh, bf16* __restrict__ ol, int C) {
    __shared__ float tile[F * (LT + 4)];
    __shared__ float hL[F], hR[F];
    const int tid = threadIdx.x;
    const int nL = 2048 / LT;
    const int bc = blockIdx.x / nL;
    const int l0 = (blockIdx.x % nL) * LT;
    const int c = bc % C;
    const float* rowbase = in + (long long)bc * F * 2048LL + l0;

    /* cooperative tile load: F*LT/4 float4 = 2048 -> 8 per thread */
#pragma unroll
    for (int i = 0; i < 8; i++) {
        int idx = tid + i * 256;
        int f = idx / (LT / 4);
        int c4 = (idx % (LT / 4)) << 2;
        float4 v = *(const float4*)(rowbase + (long long)f * 2048 + c4);
        *(float4*)(tile + f * (LT + 4) + c4) = v;
    }
    if (tid < F) hL[tid] = (l0 > 0) ? rowbase[(long long)tid * 2048 - 1] : 0.f;
    else if (tid < 2 * F) {
        int f = tid - F;
        hR[f] = (l0 + LT < 2048) ? rowbase[(long long)f * 2048 + LT] : 0.f;
    }
    float wreg[15];
#pragma unroll
    for (int i = 0; i < 15; i++) wreg[i] = w[c * 15 + i];
    __syncthreads();

    const int fq = tid / (LT / 8);
    const int lx = (tid % (LT / 8)) << 3;
    const int f0q = fq << 2;
    float a[4][8];
#pragma unroll
    for (int fo = 0; fo < 4; fo++)
#pragma unroll
        for (int j = 0; j < 8; j++) a[fo][j] = 0.f;
#pragma unroll
    for (int fi = 0; fi < 8; fi++) {
        int fr = f0q + fi - 2;
        if (fr < 0 || fr >= F) continue;
        const float* trow = tile + fr * (LT + 4);
        float x[10];
        x[0] = (lx > 0) ? trow[lx - 1] : hL[fr];
#pragma unroll
        for (int j = 1; j < 9; j++) x[j] = trow[lx + j - 1];
        x[9] = (lx + 8 < LT) ? trow[lx + 8] : hR[fr];
#pragma unroll
        for (int fo = 0; fo < 4; fo++) {
            int df = fi - fo;
            if (df < 0 || df > 4) continue;
            float w0 = wreg[df * 3 + 0], w1 = wreg[df * 3 + 1], w2 = wreg[df * 3 + 2];
#pragma unroll
            for (int j = 0; j < 8; j++)
                a[fo][j] = fmaf(w0, x[j], fmaf(w1, x[j + 1], fmaf(w2, x[j + 2], a[fo][j])));
        }
    }
#pragma unroll
    for (int fo = 0; fo < 4; fo++) {
        long long o = ((long long)bc * F + f0q + fo) * 2048LL + l0 + lx;
        st_split4(oh, ol, o,     mp_siluf(a[fo][0]), mp_siluf(a[fo][1]),
                                 mp_siluf(a[fo][2]), mp_siluf(a[fo][3]));
        st_split4(oh, ol, o + 4, mp_siluf(a[fo][4]), mp_siluf(a[fo][5]),
                                 mp_siluf(a[fo][6]), mp_siluf(a[fo][7]));
    }
}

/* ------- freq average pool, 4 elems/thread, packed stores --------------- */
__global__ void avgpool_f(const float* __restrict__ in, bf16* __restrict__ oh,
                          bf16* __restrict__ ol,
                          int C, int F, int Fo, int s, long long total4) {
    long long t = (long long)blockIdx.x * blockDim.x + threadIdx.x;
    if (t >= total4) return;
    long long e = t << 2;
    int l = (int)(e & 2047);
    long long r = e >> 11;
    int fo = (int)(r % Fo); r /= Fo;
    int c = (int)(r % C);
    int b = (int)(r / C);
    const float* p = in + (((long long)(b * C + c)) * F + fo * s) * 2048LL + l;
    float4 sum = make_float4(0.f, 0.f, 0.f, 0.f);
    for (int j = 0; j < s; j++) {
        float4 v = *(const float4*)(p + (long long)j * 2048);
        sum.x += v.x; sum.y += v.y; sum.z += v.z; sum.w += v.w;
    }
    float is = 1.f / (float)s;
    st_split4(oh, ol, e, sum.x * is, sum.y * is, sum.z * is, sum.w * is);
}

/* ------- seq depthwise k3, 8 elems/thread ------------------------------- */
__global__ void dwconv1d_silu(const float* __restrict__ hg, const float* __restrict__ w,
                              bf16* __restrict__ oh, bf16* __restrict__ ol) {
    long long t = (long long)blockIdx.x * blockDim.x + threadIdx.x;
    if (t >= 524288LL) return;
    int l0 = (int)(t & 255) << 3;
    int c = (int)((t >> 8) & 1023);
    int b = (int)(t >> 18);
    const float* row = hg + ((long long)b * 2048 + c) * 2048LL;
    const float* wc = w + c * 3;
    float4 m0 = *(const float4*)(row + l0);
    float4 m1 = *(const float4*)(row + l0 + 4);
    float x[10];
    x[0] = (l0 > 0) ? mp_siluf(row[l0 - 1]) : 0.f;
    x[1] = mp_siluf(m0.x); x[2] = mp_siluf(m0.y);
    x[3] = mp_siluf(m0.z); x[4] = mp_siluf(m0.w);
    x[5] = mp_siluf(m1.x); x[6] = mp_siluf(m1.y);
    x[7] = mp_siluf(m1.z); x[8] = mp_siluf(m1.w);
    x[9] = (l0 + 8 < 2048) ? mp_siluf(row[l0 + 8]) : 0.f;
    float w0 = wc[0], w1 = wc[1], w2 = wc[2];
    float a[8];
#pragma unroll
    for (int j = 0; j < 8; j++)
        a[j] = fmaf(w0, x[j], fmaf(w1, x[j + 1], w2 * x[j + 2]));
    long long o = ((long long)b * 1024 + c) * 2048LL + l0;
    st_split4(oh, ol, o,     mp_siluf(a[0]), mp_siluf(a[1]), mp_siluf(a[2]), mp_siluf(a[3]));
    st_split4(oh, ol, o + 4, mp_siluf(a[4]), mp_siluf(a[5]), mp_siluf(a[6]), mp_siluf(a[7]));
}

/* --------- minGRU blocked scan (4 elems/lane) + output gate ------------- */
__global__ void gru_scan(const float* __restrict__ u, const float* __restrict__ hg,
                         bf16* __restrict__ oh, bf16* __restrict__ ol) {
    int w = (int)((blockIdx.x * blockDim.x + threadIdx.x) >> 5);
    int lane = threadIdx.x & 31;
    if (w >= 2048) return;
    int bt = w >> 10, c = w & 1023;
    const float* zrow = u + ((long long)bt * 2048 + c) * 2048LL;
    const float* crow = zrow + 1024LL * 2048LL;
    const float* grow = hg + ((long long)bt * 2048 + 1024 + c) * 2048LL;
    long long obase = ((long long)bt * 1024 + c) * 2048LL;
    float carry = 0.f;
    for (int l0 = 0; l0 < 2048; l0 += 128) {
        int le = l0 + lane * 4;
        float4 zv = *(const float4*)(zrow + le);
        float4 cv = *(const float4*)(crow + le);
        float z0 = sigmoidf_fast(zv.x), z1 = sigmoidf_fast(zv.y);
        float z2 = sigmoidf_fast(zv.z), z3 = sigmoidf_fast(zv.w);
        float a0 = 1.f - z0, b0 = z0 * cv.x;
        float a1 = 1.f - z1, b1 = z1 * cv.y;
        float a2 = 1.f - z2, b2 = z2 * cv.z;
        float a3 = 1.f - z3, b3 = z3 * cv.w;
        float A = a0, B = b0;
        A = a1 * A; B = fmaf(a1, B, b1);
        A = a2 * A; B = fmaf(a2, B, b2);
        A = a3 * A; B = fmaf(a3, B, b3);
        float As = A, Bs = B;
#pragma unroll
        for (int off = 1; off < 32; off <<= 1) {
            float Ap = __shfl_up_sync(0xffffffffu, As, off);
            float Bp = __shfl_up_sync(0xffffffffu, Bs, off);
            if (lane >= off) { Bs = fmaf(As, Bp, Bs); As *= Ap; }
        }
        float Ae = __shfl_up_sync(0xffffffffu, As, 1);
        float Be = __shfl_up_sync(0xffffffffu, Bs, 1);
        if (lane == 0) { Ae = 1.f; Be = 0.f; }
        float hprev = fmaf(Ae, carry, Be);
        float h0 = fmaf(a0, hprev, b0);
        float h1 = fmaf(a1, h0, b1);
        float h2 = fmaf(a2, h1, b2);
        float h3 = fmaf(a3, h2, b3);
        carry = __shfl_sync(0xffffffffu, fmaf(As, carry, Bs), 31);
        float4 gv = *(const float4*)(grow + le);
        st_split4(oh, ol, obase + le,
                  h0 * mp_siluf(gv.x), h1 * mp_siluf(gv.y),
                  h2 * mp_siluf(gv.z), h3 * mp_siluf(gv.w));
    }
}

/* ======================================================================== */
extern "C" void kernel_launch(void* const* d_in, const int* in_sizes, int n_in,
                              void* d_out, int out_size) {
    const float* audio = (const float*)d_in[0];
    const float* pw    = (const float*)d_in[1];
    const float* pb    = (const float*)d_in[2];
    const float* c0w1  = (const float*)d_in[3];
    const float* c0wd  = (const float*)d_in[4];
    const float* c0w2  = (const float*)d_in[5];
    const float* c0dn  = (const float*)d_in[6];
    const float* c1w1  = (const float*)d_in[7];
    const float* c1wd  = (const float*)d_in[8];
    const float* c1w2  = (const float*)d_in[9];
    const float* c1dn  = (const float*)d_in[10];
    const float* c2w1  = (const float*)d_in[11];
    const float* c2wd  = (const float*)d_in[12];
    const float* c2w2  = (const float*)d_in[13];
    const float* c2dn  = (const float*)d_in[14];
    const float* hgw   = (const float*)d_in[15];
    const float* dww   = (const float*)d_in[16];
    const float* gruw  = (const float*)d_in[17];
    const float* outw  = (const float*)d_in[18];

    float *wp, *xn, *xsf, *bufA, *bufBf, *hb, *poolf, *xb;
    bf16 *wbf, *cw;
    cudaGetSymbolAddress((void**)&wp,    g_wpool);
    cudaGetSymbolAddress((void**)&xn,    g_xn);
    cudaGetSymbolAddress((void**)&xsf,   g_xs);
    cudaGetSymbolAddress((void**)&bufA,  g_bufA);
    cudaGetSymbolAddress((void**)&bufBf, g_bufB);
    cudaGetSymbolAddress((void**)&hb,    g_h);
    cudaGetSymbolAddress((void**)&poolf, g_pool);
    cudaGetSymbolAddress((void**)&xb,    g_x);
    cudaGetSymbolAddress((void**)&wbf,   g_wbf);
    cudaGetSymbolAddress((void**)&cw,    g_cwbf);

    bf16* xs   = (bf16*)xsf;
    bf16* bufB = (bf16*)bufBf;
    bf16* pool = (bf16*)poolf;
    const float* NUL = (const float*)0;

    cudaFuncSetAttribute(cgemm<128, 0>, cudaFuncAttributeMaxDynamicSharedMemorySize, 98304);
    cudaFuncSetAttribute(cgemm<128, 1>, cudaFuncAttributeMaxDynamicSharedMemorySize, 98304);
    cudaFuncSetAttribute(cgemm<128, 3>, cudaFuncAttributeMaxDynamicSharedMemorySize, 98304);
    cudaFuncSetAttribute(cgemm<64, 2>,  cudaFuncAttributeMaxDynamicSharedMemorySize, 73728);

    /* fused weight normalization + bf16 split: one launch for all 16 */
    NormDescs nd;
    {
        const float* srcs[16] = {c0w1, c0wd, c0w2, c0dn, c1w1, c1wd, c1w2, c1dn,
                                 c2w1, c2wd, c2w2, c2dn, hgw, dww, gruw, outw};
        int rows[16]   = {128, 128, 64, 128, 256, 256, 128, 256, 512, 512, 256, 512,
                          8192, 4096, 8192, 2048};
        int rowlen[16] = {64, 15, 128, 64, 128, 15, 256, 128, 256, 15, 512, 256,
                          512, 3, 1024, 1024};
        float* dstf[16] = {0, wp + O_C0WD, 0, 0, 0, wp + O_C1WD, 0, 0,
                           0, wp + O_C2WD, 0, 0, 0, wp + O_DW, 0, 0};
        int hofs[16] = {CWH_C0W1, -1, CWH_C0W2, CWH_C0DN, CWH_C1W1, -1, CWH_C1W2,
                        CWH_C1DN, CWH_C2W1, -1, CWH_C2W2, CWH_C2DN, -1, -1, -1, -1};
        int acc = 0;
        for (int i = 0; i < 16; i++) {
            acc += rows[i];
            nd.s[i].src = srcs[i];
            nd.s[i].dstf = dstf[i];
            nd.s[i].rowlen = rowlen[i];
            nd.s[i].row_end = acc;
            if (dstf[i]) { nd.s[i].dsth = 0; nd.s[i].dstl = 0; }
            else if (hofs[i] >= 0) { nd.s[i].dsth = cw + hofs[i]; nd.s[i].dstl = cw + hofs[i] + CWLO; }
        }
        nd.s[12].dsth = wbf + WH_HG(0);  nd.s[12].dstl = wbf + WH_HG(0) + WLO;
        nd.s[14].dsth = wbf + WH_GRU(0); nd.s[14].dstl = wbf + WH_GRU(0) + WLO;
        nd.s[15].dsth = wbf + WH_OUT(0); nd.s[15].dstl = wbf + WH_OUT(0) + WLO;
        norm_rows_multi<<<acc, 128>>>(nd);
    }

    /* block 0  (C 64->128->64->pool4->128, F=128, P=262144) */
    proj_pixelnorm<<<512, 256>>>(audio, pw, pb, xs, xs + XS_LO);
    cgemm<128, 0><<<dim3(2048, 1, 2), 256, 98304>>>(cw + CWH_C0W1, cw + CWH_C0W1 + CWLO,
        xs, xs + XS_LO, bufA, NUL, NUL, NUL, NUL, 128, 64, 262144LL);
    dwconv2d_silu_t<128, 64><<<8192, 256>>>(bufA, wp + O_C0WD, bufB, bufB + BUFB_LO, 128);
    cgemm<64, 2><<<dim3(2048, 1, 2), 256, 73728>>>(cw + CWH_C0W2, cw + CWH_C0W2 + CWLO,
        bufB, bufB + BUFB_LO, hb, NUL, audio, pw, pb, 64, 128, 262144LL);
    avgpool_f<<<8192, 256>>>(hb, pool, pool + POOL_LO, 64, 128, 32, 4, 2097152LL);
    cgemm<128, 0><<<dim3(512, 1, 2), 256, 98304>>>(cw + CWH_C0DN, cw + CWH_C0DN + CWLO,
        pool, pool + POOL_LO, xb, NUL, NUL, NUL, NUL, 128, 64, 65536LL);

    /* block 1  (C 128->256->128->pool4->256, F=32, P=65536) */
    pixelnorm4<true><<<128, 256>>>(xb, xn, xs, xs + XS_LO, 128, 65536LL, 131072LL);
    cgemm<128, 0><<<dim3(512, 2, 2), 256, 98304>>>(cw + CWH_C1W1, cw + CWH_C1W1 + CWLO,
        xs, xs + XS_LO, bufA, NUL, NUL, NUL, NUL, 256, 128, 65536LL);
    dwconv2d_silu_t<32, 256><<<4096, 256>>>(bufA, wp + O_C1WD, bufB, bufB + BUFB_LO, 256);
    cgemm<128, 1><<<dim3(512, 1, 2), 256, 98304>>>(cw + CWH_C1W2, cw + CWH_C1W2 + CWLO,
        bufB, bufB + BUFB_LO, hb, xn, NUL, NUL, NUL, 128, 256, 65536LL);
    avgpool_f<<<4096, 256>>>(hb, pool, pool + POOL_LO, 128, 32, 8, 4, 1048576LL);
    cgemm<128, 0><<<dim3(128, 2, 2), 256, 98304>>>(cw + CWH_C1DN, cw + CWH_C1DN + CWLO,
        pool, pool + POOL_LO, xb, NUL, NUL, NUL, NUL, 256, 128, 16384LL);

    /* block 2  (C 256->512->256->pool8->512, F=8, P=16384) */
    pixelnorm4<true><<<32, 256>>>(xb, xn, xs, xs + XS_LO, 256, 16384LL, 32768LL);
    cgemm<128, 0><<<dim3(128, 4, 2), 256, 98304>>>(cw + CWH_C2W1, cw + CWH_C2W1 + CWLO,
        xs, xs + XS_LO, bufA, NUL, NUL, NUL, NUL, 512, 256, 16384LL);
    dwconv2d_silu_t<8, 1024><<<2048, 256>>>(bufA, wp + O_C2WD, bufB, bufB + BUFB_LO, 512);
    cgemm<128, 1><<<dim3(128, 2, 2), 256, 98304>>>(cw + CWH_C2W2, cw + CWH_C2W2 + CWLO,
        bufB, bufB + BUFB_LO, hb, xn, NUL, NUL, NUL, 256, 512, 16384LL);
    avgpool_f<<<1024, 256>>>(hb, pool, pool + POOL_LO, 256, 8, 1, 8, 262144LL);
    cgemm<128, 0><<<dim3(16, 4, 2), 256, 98304>>>(cw + CWH_C2DN, cw + CWH_C2DN + CWLO,
        pool, pool + POOL_LO, xb, NUL, NUL, NUL, NUL, 512, 256, 2048LL);

    /* seq blocks ×4  (C=512, L=2048); last out-GEMM fuses final silu */
    for (int i = 0; i < 4; i++) {
        pixelnorm_s<<<128, 32>>>(xb, xn, xs, xs + XS_LO, 512, 2048LL, 4096LL);
        cgemm<128, 0><<<dim3(16, 16, 2), 256, 98304>>>(
            wbf + WH_HG(i), wbf + WH_HG(i) + WLO, xs, xs + XS_LO,
            bufA, NUL, NUL, NUL, NUL, 2048, 512, 2048LL);
        dwconv1d_silu<<<2048, 256>>>(bufA, wp + O_DW + i * 3072, bufB, bufB + BUFB_LO);
        cgemm<128, 0><<<dim3(16, 16, 2), 256, 98304>>>(
            wbf + WH_GRU(i), wbf + WH_GRU(i) + WLO, bufB, bufB + BUFB_LO,
            hb, NUL, NUL, NUL, NUL, 2048, 1024, 2048LL);
        gru_scan<<<256, 256>>>(hb, bufA, pool, pool + POOL_LO);
        if (i < 3) {
            cgemm<128, 1><<<dim3(16, 4, 2), 256, 98304>>>(
                wbf + WH_OUT(i), wbf + WH_OUT(i) + WLO, pool, pool + POOL_LO,
                xb, xn, NUL, NUL, NUL, 512, 1024, 2048LL);
        } else {
            cgemm<128, 3><<<dim3(16, 4, 2), 256, 98304>>>(
                wbf + WH_OUT(i), wbf + WH_OUT(i) + WLO, pool, pool + POOL_LO,
                (float*)d_out, xn, NUL, NUL, NUL, 512, 1024, 2048LL);
        }
    }
}